// round 2
// baseline (speedup 1.0000x reference)
#include <cuda_runtime.h>
#include <cuda_bf16.h>

#define SEQ 2048
#define H 1024
#define L 4
#define NSTEPS (SEQ + L - 1)
#define NBLOCKS 148
#define NTHREADS 1024

// ------------------------- device scratch (no allocs) -------------------------
__device__ __nv_bfloat16 g_Wb[(size_t)L * H * 4 * H];        // [l][i][gate][k] bf16
__device__ __nv_bfloat16 g_UHb[(size_t)(L - 1) * H * 4 * H]; // [l-1][i][gate][k] bf16
__device__ float g_Zin[(size_t)SEQ * 4 * H];                 // [t][gate*H + i]
__device__ float g_h[2][L * H];                              // double-buffered by t&1
__device__ float g_s[L * H];
__device__ unsigned g_bar_count;
__device__ volatile unsigned g_bar_gen;

// ------------------------- weight pack: fp32 -> bf16, gate-interleaved --------
__global__ void prep_weights(const float* __restrict__ Wf, const float* __restrict__ Wg,
                             const float* __restrict__ Wq, const float* __restrict__ Wc,
                             const float* __restrict__ UHf, const float* __restrict__ UHg,
                             const float* __restrict__ UHq, const float* __restrict__ UHc)
{
    const size_t WTOT = (size_t)L * H * 4 * H;
    const size_t UTOT = (size_t)(L - 1) * H * 4 * H;
    size_t idx = (size_t)blockIdx.x * blockDim.x + threadIdx.x;
    if (idx < WTOT) {
        int k = (int)(idx & (H - 1));
        size_t r = idx >> 10;
        int g = (int)(r & 3);
        size_t li = r >> 2;                      // l*H + i
        const float* src = (g == 0) ? Wf : (g == 1) ? Wg : (g == 2) ? Wq : Wc;
        g_Wb[idx] = __float2bfloat16(src[li * H + k]);
    } else if (idx < WTOT + UTOT) {
        size_t j = idx - WTOT;
        int k = (int)(j & (H - 1));
        size_t r = j >> 10;
        int g = (int)(r & 3);
        size_t li = r >> 2;                      // (l-1)*H + i
        const float* src = (g == 0) ? UHf : (g == 1) ? UHg : (g == 2) ? UHq : UHc;
        g_UHb[j] = __float2bfloat16(src[li * H + k]);
    }
}

__global__ void init_state()
{
    int tid = threadIdx.x;
    for (int i = tid; i < L * H; i += blockDim.x) {
        g_h[0][i] = 0.f;
        g_h[1][i] = 0.f;
        g_s[i]    = 0.f;
    }
    if (tid == 0) { g_bar_count = 0u; g_bar_gen = 0u; }
}

// ------------------------- Zin GEMM: C[t][g*H+i] = sum_k x[t][k] * U_g[i][k] ---
#define BM 128
#define BN 128
#define BK 16
__global__ __launch_bounds__(256) void gemm_zin(
    const float* __restrict__ A,                  // x [SEQ][H]
    const float* __restrict__ U0, const float* __restrict__ U1,
    const float* __restrict__ U2, const float* __restrict__ U3)
{
    __shared__ __align__(16) float As[BK][BM];
    __shared__ __align__(16) float Bs[BK][BN];
    const int tid = threadIdx.x;
    const int bm = blockIdx.y * BM;
    const int bn = blockIdx.x * BN;
    const int gate = bn >> 10;                    // 128-wide tile never spans gates
    const float* Bp = ((gate == 0) ? U0 : (gate == 1) ? U1 : (gate == 2) ? U2 : U3)
                      + (size_t)(bn & (H - 1)) * H;
    const int lr = tid & 63;
    const int gq = tid >> 6;                      // 0..3 (k-quad)
    const int tx = tid & 15, ty = tid >> 4;

    float acc[8][8];
#pragma unroll
    for (int i = 0; i < 8; ++i)
#pragma unroll
        for (int j = 0; j < 8; ++j) acc[i][j] = 0.f;

    for (int k0 = 0; k0 < H; k0 += BK) {
        float4 a0 = *(const float4*)(A + (size_t)(bm + lr) * H + k0 + gq * 4);
        float4 a1 = *(const float4*)(A + (size_t)(bm + lr + 64) * H + k0 + gq * 4);
        float4 b0 = *(const float4*)(Bp + (size_t)lr * H + k0 + gq * 4);
        float4 b1 = *(const float4*)(Bp + (size_t)(lr + 64) * H + k0 + gq * 4);
        As[gq * 4 + 0][lr] = a0.x; As[gq * 4 + 1][lr] = a0.y;
        As[gq * 4 + 2][lr] = a0.z; As[gq * 4 + 3][lr] = a0.w;
        As[gq * 4 + 0][lr + 64] = a1.x; As[gq * 4 + 1][lr + 64] = a1.y;
        As[gq * 4 + 2][lr + 64] = a1.z; As[gq * 4 + 3][lr + 64] = a1.w;
        Bs[gq * 4 + 0][lr] = b0.x; Bs[gq * 4 + 1][lr] = b0.y;
        Bs[gq * 4 + 2][lr] = b0.z; Bs[gq * 4 + 3][lr] = b0.w;
        Bs[gq * 4 + 0][lr + 64] = b1.x; Bs[gq * 4 + 1][lr + 64] = b1.y;
        Bs[gq * 4 + 2][lr + 64] = b1.z; Bs[gq * 4 + 3][lr + 64] = b1.w;
        __syncthreads();
#pragma unroll
        for (int kk = 0; kk < BK; ++kk) {
            float4 a0r = *(const float4*)&As[kk][ty * 8];
            float4 a1r = *(const float4*)&As[kk][ty * 8 + 4];
            float4 b0r = *(const float4*)&Bs[kk][tx * 8];
            float4 b1r = *(const float4*)&Bs[kk][tx * 8 + 4];
            float ar[8] = {a0r.x, a0r.y, a0r.z, a0r.w, a1r.x, a1r.y, a1r.z, a1r.w};
            float br[8] = {b0r.x, b0r.y, b0r.z, b0r.w, b1r.x, b1r.y, b1r.z, b1r.w};
#pragma unroll
            for (int i = 0; i < 8; ++i)
#pragma unroll
                for (int j = 0; j < 8; ++j)
                    acc[i][j] = fmaf(ar[i], br[j], acc[i][j]);
        }
        __syncthreads();
    }
#pragma unroll
    for (int i = 0; i < 8; ++i) {
        int m = bm + ty * 8 + i;
        float* crow = g_Zin + (size_t)m * (4 * H) + bn + tx * 8;
#pragma unroll
        for (int j = 0; j < 8; j += 4) {
            *(float4*)(crow + j) = make_float4(acc[i][j], acc[i][j + 1],
                                               acc[i][j + 2], acc[i][j + 3]);
        }
    }
}

// ------------------------- grid-wide barrier (all blocks resident) ------------
__device__ __forceinline__ void grid_barrier()
{
    __syncthreads();
    if (threadIdx.x == 0) {
        __threadfence();
        unsigned gen = g_bar_gen;
        unsigned arrived = atomicAdd(&g_bar_count, 1u);
        if (arrived == gridDim.x - 1) {
            atomicExch(&g_bar_count, 0u);
            __threadfence();
            g_bar_gen = gen + 1u;
        } else {
            while (g_bar_gen == gen) { __nanosleep(32); }
        }
        __threadfence();
    }
    __syncthreads();
}

// ------------------------- matvec core ----------------------------------------
__device__ __forceinline__ float dot8(uint4 w, float4 h0, float4 h1, float acc)
{
    const __nv_bfloat162* p = reinterpret_cast<const __nv_bfloat162*>(&w);
    float2 f0 = __bfloat1622float2(p[0]);
    float2 f1 = __bfloat1622float2(p[1]);
    float2 f2 = __bfloat1622float2(p[2]);
    float2 f3 = __bfloat1622float2(p[3]);
    acc = fmaf(f0.x, h0.x, acc); acc = fmaf(f0.y, h0.y, acc);
    acc = fmaf(f1.x, h0.z, acc); acc = fmaf(f1.y, h0.w, acc);
    acc = fmaf(f2.x, h1.x, acc); acc = fmaf(f2.y, h1.y, acc);
    acc = fmaf(f3.x, h1.z, acc); acc = fmaf(f3.y, h1.w, acc);
    return acc;
}

// 4 stacked gate rows (bf16, gate-interleaved) dotted against hvec (shared mem)
__device__ __forceinline__ void mv4(const __nv_bfloat16* __restrict__ Wrow,
                                    const float* __restrict__ hvec,
                                    int lane, float acc[4])
{
    const uint4* wr = reinterpret_cast<const uint4*>(Wrow);
#pragma unroll
    for (int c = 0; c < 4; ++c) {
        const float4* hp = reinterpret_cast<const float4*>(hvec + c * 256 + lane * 8);
        float4 h0 = hp[0];
        float4 h1 = hp[1];
#pragma unroll
        for (int g = 0; g < 4; ++g) {
            uint4 w = wr[g * 128 + c * 32 + lane];
            acc[g] = dot8(w, h0, h1, acc[g]);
        }
    }
}

// ------------------------- persistent wavefront LSTM --------------------------
__global__ __launch_bounds__(NTHREADS, 1) void lstm_main(
    const float* __restrict__ Bf, const float* __restrict__ Bg,
    const float* __restrict__ Bq, const float* __restrict__ Bc,
    float* __restrict__ out)
{
    __shared__ __align__(16) float sh_prev[4][H];
    __shared__ __align__(16) float sh_in[4][H];
    const int tid = threadIdx.x;
    const int lane = tid & 31;
    const int gwarp = blockIdx.x * (NTHREADS / 32) + (tid >> 5);
    const int NW = gridDim.x * (NTHREADS / 32);

    for (int step = 0; step < NSTEPS; ++step) {
        const int lmin = (step > SEQ - 1) ? (step - (SEQ - 1)) : 0;
        const int lmax = (step < L - 1) ? step : (L - 1);
        const int ncells = lmax - lmin + 1;

        // Stage h vectors for this wavefront into SMEM (L2-coherent loads).
        for (int idx = tid; idx < (ncells << 10); idx += NTHREADS) {
            int ci = idx >> 10, i = idx & (H - 1);
            int l = lmin + ci, t = step - l;
            sh_prev[ci][i] = __ldcg(&g_h[(t + 1) & 1][l * H + i]);
            if (l > 0) sh_in[ci][i] = __ldcg(&g_h[t & 1][(l - 1) * H + i]);
        }
        __syncthreads();

        const int ntasks = ncells << 10;
        for (int task = gwarp; task < ntasks; task += NW) {
            int ci = task >> 10, i = task & (H - 1);
            int l = lmin + ci, t = step - l;

            float acc[4] = {0.f, 0.f, 0.f, 0.f};
            mv4(g_Wb + (size_t)(l * H + i) * (4 * H), sh_prev[ci], lane, acc);
            if (l > 0)
                mv4(g_UHb + (size_t)((l - 1) * H + i) * (4 * H), sh_in[ci], lane, acc);

#pragma unroll
            for (int off = 16; off > 0; off >>= 1) {
                acc[0] += __shfl_xor_sync(0xffffffffu, acc[0], off);
                acc[1] += __shfl_xor_sync(0xffffffffu, acc[1], off);
                acc[2] += __shfl_xor_sync(0xffffffffu, acc[2], off);
                acc[3] += __shfl_xor_sync(0xffffffffu, acc[3], off);
            }

            if (lane == 0) {
                const int bi = l * H + i;
                float zf = acc[0] + Bf[bi];
                float zg = acc[1] + Bg[bi];
                float zq = acc[2] + Bq[bi];
                float zc = acc[3] + Bc[bi];
                if (l == 0) {
                    const float* zin = g_Zin + (size_t)t * (4 * H);
                    zf += zin[i];
                    zg += zin[H + i];
                    zq += zin[2 * H + i];
                    zc += zin[3 * H + i];
                }
                float f  = 1.f / (1.f + __expf(-zf));
                float gg = 1.f / (1.f + __expf(-zg));
                float q  = 1.f / (1.f + __expf(-zq));
                float cd = 1.f / (1.f + __expf(-zc));
                float sp = __ldcg(&g_s[bi]);
                float sn = fmaf(f, sp, gg * cd);
                g_s[bi] = sn;
                float hn = tanhf(sn) * q;
                g_h[t & 1][bi] = hn;
                if (t == SEQ - 1) out[bi] = hn;
            }
        }
        grid_barrier();
    }
}

// ------------------------- launch ---------------------------------------------
extern "C" void kernel_launch(void* const* d_in, const int* in_sizes, int n_in,
                              void* d_out, int out_size)
{
    const float* x   = (const float*)d_in[0];
    const float* Uf  = (const float*)d_in[1];
    const float* UHf = (const float*)d_in[2];
    const float* Wf  = (const float*)d_in[3];
    const float* Bf  = (const float*)d_in[4];
    const float* Ug  = (const float*)d_in[5];
    const float* UHg = (const float*)d_in[6];
    const float* Wg  = (const float*)d_in[7];
    const float* Bg  = (const float*)d_in[8];
    const float* Uq  = (const float*)d_in[9];
    const float* UHq = (const float*)d_in[10];
    const float* Wq  = (const float*)d_in[11];
    const float* Bq  = (const float*)d_in[12];
    const float* Uc  = (const float*)d_in[13];
    const float* UHc = (const float*)d_in[14];
    const float* Wc  = (const float*)d_in[15];
    const float* Bc  = (const float*)d_in[16];
    float* out = (float*)d_out;

    const size_t TOTAL = (size_t)L * H * 4 * H + (size_t)(L - 1) * H * 4 * H;
    int pb = (int)((TOTAL + 1023) / 1024);
    prep_weights<<<pb, 1024>>>(Wf, Wg, Wq, Wc, UHf, UHg, UHq, UHc);
    init_state<<<1, 1024>>>();

    dim3 gg(4 * H / BN, SEQ / BM);
    gemm_zin<<<gg, 256>>>(x, Uf, Ug, Uq, Uc);

    lstm_main<<<NBLOCKS, NTHREADS>>>(Bf, Bg, Bq, Bc, out);
}

// round 3
// speedup vs baseline: 1.2598x; 1.2598x over previous
#include <cuda_runtime.h>
#include <cuda_bf16.h>
#include <cuda_fp16.h>
#include <cuda_fp8.h>

#define SEQ 2048
#define H 1024
#define L 4
#define NSTEPS (SEQ + L - 1)
#define NBLOCKS 148
#define NTHREADS 1024

// ------------------------- device scratch (no allocs) -------------------------
// fp8 weights, layout per (l,i): [gate][k], 4096 bytes per row-task
__device__ unsigned char g_Wb8[(size_t)L * H * 4 * H];        // 16 MB
__device__ unsigned char g_UHb8[(size_t)(L - 1) * H * 4 * H]; // 12 MB
__device__ float g_Zin[(size_t)SEQ * 4 * H];                  // [t][gate*H + i]
__device__ float g_h[2][L * H];                               // double-buffered by t&1
__device__ float g_s[L * H];
__device__ unsigned g_bar_count;
__device__ volatile unsigned g_bar_gen;

// ------------------------- weight pack: fp32 -> fp8 e4m3 ----------------------
__global__ void prep_weights(const float* __restrict__ Wf, const float* __restrict__ Wg,
                             const float* __restrict__ Wq, const float* __restrict__ Wc,
                             const float* __restrict__ UHf, const float* __restrict__ UHg,
                             const float* __restrict__ UHq, const float* __restrict__ UHc)
{
    const size_t WTOT = (size_t)L * H * 4 * H;
    const size_t UTOT = (size_t)(L - 1) * H * 4 * H;
    size_t idx = (size_t)blockIdx.x * blockDim.x + threadIdx.x;
    if (idx < WTOT) {
        int k = (int)(idx & (H - 1));
        size_t r = idx >> 10;
        int g = (int)(r & 3);
        size_t li = r >> 2;                       // l*H + i
        const float* src = (g == 0) ? Wf : (g == 1) ? Wg : (g == 2) ? Wq : Wc;
        g_Wb8[idx] = (unsigned char)__nv_cvt_float_to_fp8(src[li * H + k],
                                                          __NV_SATFINITE, __NV_E4M3);
    } else if (idx < WTOT + UTOT) {
        size_t j = idx - WTOT;
        int k = (int)(j & (H - 1));
        size_t r = j >> 10;
        int g = (int)(r & 3);
        size_t li = r >> 2;                       // (l-1)*H + i
        const float* src = (g == 0) ? UHf : (g == 1) ? UHg : (g == 2) ? UHq : UHc;
        g_UHb8[j] = (unsigned char)__nv_cvt_float_to_fp8(src[li * H + k],
                                                         __NV_SATFINITE, __NV_E4M3);
    }
}

__global__ void init_state()
{
    int tid = threadIdx.x;
    for (int i = tid; i < L * H; i += blockDim.x) {
        g_h[0][i] = 0.f;
        g_h[1][i] = 0.f;
        g_s[i]    = 0.f;
    }
    if (tid == 0) { g_bar_count = 0u; g_bar_gen = 0u; }
}

// ------------------------- Zin GEMM: C[t][g*H+i] = sum_k x[t][k] * U_g[i][k] ---
#define BM 128
#define BN 128
#define BK 16
__global__ __launch_bounds__(256) void gemm_zin(
    const float* __restrict__ A,                  // x [SEQ][H]
    const float* __restrict__ U0, const float* __restrict__ U1,
    const float* __restrict__ U2, const float* __restrict__ U3)
{
    __shared__ __align__(16) float As[BK][BM];
    __shared__ __align__(16) float Bs[BK][BN];
    const int tid = threadIdx.x;
    const int bm = blockIdx.y * BM;
    const int bn = blockIdx.x * BN;
    const int gate = bn >> 10;                    // 128-wide tile never spans gates
    const float* Bp = ((gate == 0) ? U0 : (gate == 1) ? U1 : (gate == 2) ? U2 : U3)
                      + (size_t)(bn & (H - 1)) * H;
    const int lr = tid & 63;
    const int gq = tid >> 6;                      // 0..3 (k-quad)
    const int tx = tid & 15, ty = tid >> 4;

    float acc[8][8];
#pragma unroll
    for (int i = 0; i < 8; ++i)
#pragma unroll
        for (int j = 0; j < 8; ++j) acc[i][j] = 0.f;

    for (int k0 = 0; k0 < H; k0 += BK) {
        float4 a0 = *(const float4*)(A + (size_t)(bm + lr) * H + k0 + gq * 4);
        float4 a1 = *(const float4*)(A + (size_t)(bm + lr + 64) * H + k0 + gq * 4);
        float4 b0 = *(const float4*)(Bp + (size_t)lr * H + k0 + gq * 4);
        float4 b1 = *(const float4*)(Bp + (size_t)(lr + 64) * H + k0 + gq * 4);
        As[gq * 4 + 0][lr] = a0.x; As[gq * 4 + 1][lr] = a0.y;
        As[gq * 4 + 2][lr] = a0.z; As[gq * 4 + 3][lr] = a0.w;
        As[gq * 4 + 0][lr + 64] = a1.x; As[gq * 4 + 1][lr + 64] = a1.y;
        As[gq * 4 + 2][lr + 64] = a1.z; As[gq * 4 + 3][lr + 64] = a1.w;
        Bs[gq * 4 + 0][lr] = b0.x; Bs[gq * 4 + 1][lr] = b0.y;
        Bs[gq * 4 + 2][lr] = b0.z; Bs[gq * 4 + 3][lr] = b0.w;
        Bs[gq * 4 + 0][lr + 64] = b1.x; Bs[gq * 4 + 1][lr + 64] = b1.y;
        Bs[gq * 4 + 2][lr + 64] = b1.z; Bs[gq * 4 + 3][lr + 64] = b1.w;
        __syncthreads();
#pragma unroll
        for (int kk = 0; kk < BK; ++kk) {
            float4 a0r = *(const float4*)&As[kk][ty * 8];
            float4 a1r = *(const float4*)&As[kk][ty * 8 + 4];
            float4 b0r = *(const float4*)&Bs[kk][tx * 8];
            float4 b1r = *(const float4*)&Bs[kk][tx * 8 + 4];
            float ar[8] = {a0r.x, a0r.y, a0r.z, a0r.w, a1r.x, a1r.y, a1r.z, a1r.w};
            float br[8] = {b0r.x, b0r.y, b0r.z, b0r.w, b1r.x, b1r.y, b1r.z, b1r.w};
#pragma unroll
            for (int i = 0; i < 8; ++i)
#pragma unroll
                for (int j = 0; j < 8; ++j)
                    acc[i][j] = fmaf(ar[i], br[j], acc[i][j]);
        }
        __syncthreads();
    }
#pragma unroll
    for (int i = 0; i < 8; ++i) {
        int m = bm + ty * 8 + i;
        float* crow = g_Zin + (size_t)m * (4 * H) + bn + tx * 8;
#pragma unroll
        for (int j = 0; j < 8; j += 4) {
            *(float4*)(crow + j) = make_float4(acc[i][j], acc[i][j + 1],
                                               acc[i][j + 2], acc[i][j + 3]);
        }
    }
}

// ------------------------- grid-wide barrier (all blocks resident) ------------
__device__ __forceinline__ void grid_barrier()
{
    __syncthreads();
    if (threadIdx.x == 0) {
        __threadfence();
        unsigned gen = g_bar_gen;
        unsigned arrived = atomicAdd(&g_bar_count, 1u);
        if (arrived == gridDim.x - 1) {
            atomicExch(&g_bar_count, 0u);
            __threadfence();
            g_bar_gen = gen + 1u;
        } else {
            while (g_bar_gen == gen) { }   // pure spin: wake = one L2 round trip
        }
        __threadfence();
    }
    __syncthreads();
}

// ------------------------- fp8 -> half2 convert --------------------------------
__device__ __forceinline__ __half2 cvt_e4m3x2(unsigned short v)
{
    unsigned r;
    asm("cvt.rn.f16x2.e4m3x2 %0, %1;" : "=r"(r) : "h"(v));
    return *reinterpret_cast<__half2*>(&r);
}

// Process one 4-gate fp8 weight batch (8 uint4, already loaded) against hvec.
__device__ __forceinline__ void process8(const uint4 w[8],
                                         const __half2* __restrict__ hvec,
                                         int lane, __half2 acc2[4])
{
    const uint4* hp = reinterpret_cast<const uint4*>(hvec);
#pragma unroll
    for (int c = 0; c < 2; ++c) {
        // k-range: c*512 + lane*16 (halves) -> uint4 index c*64 + lane*2
        uint4 ha = hp[c * 64 + lane * 2];
        uint4 hb = hp[c * 64 + lane * 2 + 1];
        __half2 hv[8];
        *reinterpret_cast<uint4*>(&hv[0]) = ha;
        *reinterpret_cast<uint4*>(&hv[4]) = hb;
#pragma unroll
        for (int g = 0; g < 4; ++g) {
            const unsigned short* ws = reinterpret_cast<const unsigned short*>(&w[g * 2 + c]);
#pragma unroll
            for (int j = 0; j < 8; ++j)
                acc2[g] = __hfma2(cvt_e4m3x2(ws[j]), hv[j], acc2[g]);
        }
    }
}

// ------------------------- persistent wavefront LSTM --------------------------
__global__ __launch_bounds__(NTHREADS, 1) void lstm_main(
    const float* __restrict__ Bf, const float* __restrict__ Bg,
    const float* __restrict__ Bq, const float* __restrict__ Bc,
    float* __restrict__ out)
{
    __shared__ __align__(16) __half2 sh_prev[4][H / 2];
    __shared__ __align__(16) __half2 sh_in[4][H / 2];
    const int tid = threadIdx.x;
    const int lane = tid & 31;
    const int gwarp = blockIdx.x * (NTHREADS / 32) + (tid >> 5);
    const int NW = gridDim.x * (NTHREADS / 32);

    for (int step = 0; step < NSTEPS; ++step) {
        const int lmin = (step > SEQ - 1) ? (step - (SEQ - 1)) : 0;
        const int lmax = (step < L - 1) ? step : (L - 1);
        const int ncells = lmax - lmin + 1;

        // Stage h vectors (f32 -> half2) for this wavefront into SMEM.
        for (int idx = tid; idx < (ncells << 9); idx += NTHREADS) {
            int ci = idx >> 9, j = idx & (H / 2 - 1);
            int l = lmin + ci, t = step - l;
            const float2* hp = reinterpret_cast<const float2*>(&g_h[(t + 1) & 1][l * H]);
            float2 v = __ldcg(hp + j);
            sh_prev[ci][j] = __floats2half2_rn(v.x, v.y);
            if (l > 0) {
                const float2* hq = reinterpret_cast<const float2*>(&g_h[t & 1][(l - 1) * H]);
                float2 u = __ldcg(hq + j);
                sh_in[ci][j] = __floats2half2_rn(u.x, u.y);
            }
        }
        __syncthreads();

        const int ntasks = ncells << 10;
        for (int task = gwarp; task < ntasks; task += NW) {
            int ci = task >> 10, i = task & (H - 1);
            int l = lmin + ci, t = step - l;

            __half2 acc2[4];
            const __half2 hz = __float2half2_rn(0.f);
            acc2[0] = hz; acc2[1] = hz; acc2[2] = hz; acc2[3] = hz;

            // ---- W batch: 8 back-to-back 16B loads (full 4-gate row) ----
            {
                const uint4* wr = reinterpret_cast<const uint4*>(
                    g_Wb8 + (size_t)(l * H + i) * (4 * H));
                uint4 w[8];
#pragma unroll
                for (int g = 0; g < 4; ++g)
#pragma unroll
                    for (int c = 0; c < 2; ++c)
                        w[g * 2 + c] = __ldcg(&wr[g * 64 + c * 32 + lane]);
                process8(w, sh_prev[ci], lane, acc2);
            }
            // ---- UH batch ----
            if (l > 0) {
                const uint4* ur = reinterpret_cast<const uint4*>(
                    g_UHb8 + (size_t)((l - 1) * H + i) * (4 * H));
                uint4 w[8];
#pragma unroll
                for (int g = 0; g < 4; ++g)
#pragma unroll
                    for (int c = 0; c < 2; ++c)
                        w[g * 2 + c] = __ldcg(&ur[g * 64 + c * 32 + lane]);
                process8(w, sh_in[ci], lane, acc2);
            }

            float acc[4];
#pragma unroll
            for (int g = 0; g < 4; ++g) {
                float2 f = __half22float2(acc2[g]);
                acc[g] = f.x + f.y;
            }
#pragma unroll
            for (int off = 16; off > 0; off >>= 1) {
                acc[0] += __shfl_xor_sync(0xffffffffu, acc[0], off);
                acc[1] += __shfl_xor_sync(0xffffffffu, acc[1], off);
                acc[2] += __shfl_xor_sync(0xffffffffu, acc[2], off);
                acc[3] += __shfl_xor_sync(0xffffffffu, acc[3], off);
            }

            if (lane == 0) {
                const int bi = l * H + i;
                float zf = acc[0] + Bf[bi];
                float zg = acc[1] + Bg[bi];
                float zq = acc[2] + Bq[bi];
                float zc = acc[3] + Bc[bi];
                if (l == 0) {
                    const float* zin = g_Zin + (size_t)t * (4 * H);
                    zf += zin[i];
                    zg += zin[H + i];
                    zq += zin[2 * H + i];
                    zc += zin[3 * H + i];
                }
                float f  = 1.f / (1.f + __expf(-zf));
                float gg = 1.f / (1.f + __expf(-zg));
                float q  = 1.f / (1.f + __expf(-zq));
                float cd = 1.f / (1.f + __expf(-zc));
                float sp = __ldcg(&g_s[bi]);
                float sn = fmaf(f, sp, gg * cd);
                g_s[bi] = sn;
                float hn = tanhf(sn) * q;
                g_h[t & 1][bi] = hn;
                if (t == SEQ - 1) out[bi] = hn;
            }
        }
        grid_barrier();
    }
}

// ------------------------- launch ---------------------------------------------
extern "C" void kernel_launch(void* const* d_in, const int* in_sizes, int n_in,
                              void* d_out, int out_size)
{
    const float* x   = (const float*)d_in[0];
    const float* Uf  = (const float*)d_in[1];
    const float* UHf = (const float*)d_in[2];
    const float* Wf  = (const float*)d_in[3];
    const float* Bf  = (const float*)d_in[4];
    const float* Ug  = (const float*)d_in[5];
    const float* UHg = (const float*)d_in[6];
    const float* Wg  = (const float*)d_in[7];
    const float* Bg  = (const float*)d_in[8];
    const float* Uq  = (const float*)d_in[9];
    const float* UHq = (const float*)d_in[10];
    const float* Wq  = (const float*)d_in[11];
    const float* Bq  = (const float*)d_in[12];
    const float* Uc  = (const float*)d_in[13];
    const float* UHc = (const float*)d_in[14];
    const float* Wc  = (const float*)d_in[15];
    const float* Bc  = (const float*)d_in[16];
    float* out = (float*)d_out;

    const size_t TOTAL = (size_t)L * H * 4 * H + (size_t)(L - 1) * H * 4 * H;
    int pb = (int)((TOTAL + 1023) / 1024);
    prep_weights<<<pb, 1024>>>(Wf, Wg, Wq, Wc, UHf, UHg, UHq, UHc);
    init_state<<<1, 1024>>>();

    dim3 gg(4 * H / BN, SEQ / BM);
    gemm_zin<<<gg, 256>>>(x, Uf, Ug, Uq, Uc);

    lstm_main<<<NBLOCKS, NTHREADS>>>(Bf, Bg, Bq, Bc, out);
}

// round 4
// speedup vs baseline: 2.3376x; 1.8555x over previous
#include <cuda_runtime.h>
#include <cuda_bf16.h>
#include <cuda_fp16.h>
#include <cuda_fp8.h>

#define SEQ 2048
#define H 1024
#define L 4
#define NSTEPS (SEQ + L - 1)
#define NBLOCKS 148
#define NTHREADS 1024
#define NTASKW 28           // warps 0..27 own tasks (7 l=0 rows + 21 l>0 rows)

// SMEM: 7*4KB + 21*8KB weights = 200704 B, + 8KB h-stage = 208896 B
#define SMEM_W_BYTES 200704
#define SMEM_BYTES   (SMEM_W_BYTES + 8192)

// ------------------------- device scratch (no allocs) -------------------------
__device__ unsigned char g_Wb8[(size_t)L * H * 4 * H];        // [l][i][gate][k] fp8
__device__ unsigned char g_UHb8[(size_t)(L - 1) * H * 4 * H]; // [l-1][i][gate][k] fp8
__device__ float g_Zin[(size_t)SEQ * 4 * H];                  // [t][gate*H + i]
__device__ __align__(16) __half g_hh[2][L * H];               // h, fp16, dbl-buffered
__device__ unsigned g_bar_count;
__device__ volatile unsigned g_bar_gen;

// ------------------------- weight pack: fp32 -> fp8 e4m3 ----------------------
__global__ void prep_weights(const float* __restrict__ Wf, const float* __restrict__ Wg,
                             const float* __restrict__ Wq, const float* __restrict__ Wc,
                             const float* __restrict__ UHf, const float* __restrict__ UHg,
                             const float* __restrict__ UHq, const float* __restrict__ UHc)
{
    const size_t WTOT = (size_t)L * H * 4 * H;
    const size_t UTOT = (size_t)(L - 1) * H * 4 * H;
    size_t idx = (size_t)blockIdx.x * blockDim.x + threadIdx.x;
    if (idx < WTOT) {
        int k = (int)(idx & (H - 1));
        size_t r = idx >> 10;
        int g = (int)(r & 3);
        size_t li = r >> 2;                       // l*H + i
        const float* src = (g == 0) ? Wf : (g == 1) ? Wg : (g == 2) ? Wq : Wc;
        g_Wb8[idx] = (unsigned char)__nv_cvt_float_to_fp8(src[li * H + k],
                                                          __NV_SATFINITE, __NV_E4M3);
    } else if (idx < WTOT + UTOT) {
        size_t j = idx - WTOT;
        int k = (int)(j & (H - 1));
        size_t r = j >> 10;
        int g = (int)(r & 3);
        size_t li = r >> 2;                       // (l-1)*H + i
        const float* src = (g == 0) ? UHf : (g == 1) ? UHg : (g == 2) ? UHq : UHc;
        g_UHb8[j] = (unsigned char)__nv_cvt_float_to_fp8(src[li * H + k],
                                                         __NV_SATFINITE, __NV_E4M3);
    }
}

__global__ void init_state()
{
    int tid = threadIdx.x;
    for (int i = tid; i < L * H; i += blockDim.x) {
        g_hh[0][i] = __float2half(0.f);
        g_hh[1][i] = __float2half(0.f);
    }
    if (tid == 0) { g_bar_count = 0u; g_bar_gen = 0u; }
}

// ------------------------- Zin GEMM: C[t][g*H+i] = sum_k x[t][k] * U_g[i][k] ---
#define BM 128
#define BN 128
#define BK 16
__global__ __launch_bounds__(256) void gemm_zin(
    const float* __restrict__ A,                  // x [SEQ][H]
    const float* __restrict__ U0, const float* __restrict__ U1,
    const float* __restrict__ U2, const float* __restrict__ U3)
{
    __shared__ __align__(16) float As[BK][BM];
    __shared__ __align__(16) float Bs[BK][BN];
    const int tid = threadIdx.x;
    const int bm = blockIdx.y * BM;
    const int bn = blockIdx.x * BN;
    const int gate = bn >> 10;                    // 128-wide tile never spans gates
    const float* Bp = ((gate == 0) ? U0 : (gate == 1) ? U1 : (gate == 2) ? U2 : U3)
                      + (size_t)(bn & (H - 1)) * H;
    const int lr = tid & 63;
    const int gq = tid >> 6;                      // 0..3 (k-quad)
    const int tx = tid & 15, ty = tid >> 4;

    float acc[8][8];
#pragma unroll
    for (int i = 0; i < 8; ++i)
#pragma unroll
        for (int j = 0; j < 8; ++j) acc[i][j] = 0.f;

    for (int k0 = 0; k0 < H; k0 += BK) {
        float4 a0 = *(const float4*)(A + (size_t)(bm + lr) * H + k0 + gq * 4);
        float4 a1 = *(const float4*)(A + (size_t)(bm + lr + 64) * H + k0 + gq * 4);
        float4 b0 = *(const float4*)(Bp + (size_t)lr * H + k0 + gq * 4);
        float4 b1 = *(const float4*)(Bp + (size_t)(lr + 64) * H + k0 + gq * 4);
        As[gq * 4 + 0][lr] = a0.x; As[gq * 4 + 1][lr] = a0.y;
        As[gq * 4 + 2][lr] = a0.z; As[gq * 4 + 3][lr] = a0.w;
        As[gq * 4 + 0][lr + 64] = a1.x; As[gq * 4 + 1][lr + 64] = a1.y;
        As[gq * 4 + 2][lr + 64] = a1.z; As[gq * 4 + 3][lr + 64] = a1.w;
        Bs[gq * 4 + 0][lr] = b0.x; Bs[gq * 4 + 1][lr] = b0.y;
        Bs[gq * 4 + 2][lr] = b0.z; Bs[gq * 4 + 3][lr] = b0.w;
        Bs[gq * 4 + 0][lr + 64] = b1.x; Bs[gq * 4 + 1][lr + 64] = b1.y;
        Bs[gq * 4 + 2][lr + 64] = b1.z; Bs[gq * 4 + 3][lr + 64] = b1.w;
        __syncthreads();
#pragma unroll
        for (int kk = 0; kk < BK; ++kk) {
            float4 a0r = *(const float4*)&As[kk][ty * 8];
            float4 a1r = *(const float4*)&As[kk][ty * 8 + 4];
            float4 b0r = *(const float4*)&Bs[kk][tx * 8];
            float4 b1r = *(const float4*)&Bs[kk][tx * 8 + 4];
            float ar[8] = {a0r.x, a0r.y, a0r.z, a0r.w, a1r.x, a1r.y, a1r.z, a1r.w};
            float br[8] = {b0r.x, b0r.y, b0r.z, b0r.w, b1r.x, b1r.y, b1r.z, b1r.w};
#pragma unroll
            for (int i = 0; i < 8; ++i)
#pragma unroll
                for (int j = 0; j < 8; ++j)
                    acc[i][j] = fmaf(ar[i], br[j], acc[i][j]);
        }
        __syncthreads();
    }
#pragma unroll
    for (int i = 0; i < 8; ++i) {
        int m = bm + ty * 8 + i;
        float* crow = g_Zin + (size_t)m * (4 * H) + bn + tx * 8;
#pragma unroll
        for (int j = 0; j < 8; j += 4) {
            *(float4*)(crow + j) = make_float4(acc[i][j], acc[i][j + 1],
                                               acc[i][j + 2], acc[i][j + 3]);
        }
    }
}

// ------------------------- grid-wide barrier (all blocks resident) ------------
__device__ __forceinline__ void grid_barrier()
{
    __syncthreads();
    if (threadIdx.x == 0) {
        __threadfence();
        unsigned gen = g_bar_gen;
        unsigned arrived = atomicAdd(&g_bar_count, 1u);
        if (arrived == gridDim.x - 1) {
            atomicExch(&g_bar_count, 0u);
            __threadfence();
            g_bar_gen = gen + 1u;
        } else {
            while (g_bar_gen == gen) { }
        }
        __threadfence();
    }
    __syncthreads();
}

// ------------------------- fp8 -> half2 convert --------------------------------
__device__ __forceinline__ __half2 cvt_e4m3x2(unsigned short v)
{
    unsigned r;
    asm("cvt.rn.f16x2.e4m3x2 %0, %1;" : "=r"(r) : "h"(v));
    return *reinterpret_cast<__half2*>(&r);
}

// One 4-gate fp8 row (SMEM) dotted against a staged h vector (SMEM, split layout).
// h split layout: uint4 index (c*2+pair)*32+lane holds halves k=c*512+lane*16+pair*8..+7
__device__ __forceinline__ void mv_smem(const uint4* __restrict__ wsm,
                                        const uint4* __restrict__ hsm,
                                        int lane, __half2 acc2[4])
{
#pragma unroll
    for (int c = 0; c < 2; ++c) {
        uint4 ha = hsm[(c * 2 + 0) * 32 + lane];
        uint4 hb = hsm[(c * 2 + 1) * 32 + lane];
        __half2 hv[8];
        *reinterpret_cast<uint4*>(&hv[0]) = ha;
        *reinterpret_cast<uint4*>(&hv[4]) = hb;
#pragma unroll
        for (int g = 0; g < 4; ++g) {
            uint4 w = wsm[g * 64 + c * 32 + lane];
            const unsigned short* ws = reinterpret_cast<const unsigned short*>(&w);
#pragma unroll
            for (int j = 0; j < 8; ++j)
                acc2[g] = __hfma2(cvt_e4m3x2(ws[j]), hv[j], acc2[g]);
        }
    }
}

// ------------------------- persistent wavefront LSTM (SMEM-resident weights) --
__global__ __launch_bounds__(NTHREADS, 1) void lstm_main(
    const float* __restrict__ Bf, const float* __restrict__ Bg,
    const float* __restrict__ Bq, const float* __restrict__ Bc,
    float* __restrict__ out)
{
    extern __shared__ __align__(16) unsigned char smem[];
    unsigned char* sh_h = smem + SMEM_W_BYTES;    // 4 vectors x 2048 B (split layout)

    const int tid  = threadIdx.x;
    const int lane = tid & 31;
    const int w    = tid >> 5;

    // ---- static task assignment: warp -> (l, i) ----
    int l = -1, i = 0, woff = 0;
    bool valid = false;
    if (w < 7) {
        l = 0; i = blockIdx.x * 7 + w; woff = w * 4096;
        valid = (i < H);
    } else if (w < NTASKW) {
        int j = blockIdx.x * 21 + (w - 7);
        l = 1 + (j >> 10); i = j & (H - 1);
        woff = 28672 + (w - 7) * 8192;
        valid = (j < 3 * H);
    }
    const int bi = (valid ? l * H + i : 0);

    // ---- copy this warp's weights into SMEM (once) ----
    if (valid) {
        const uint4* srcW = reinterpret_cast<const uint4*>(g_Wb8 + (size_t)bi * 4096);
        uint4* dstW = reinterpret_cast<uint4*>(smem + woff);
#pragma unroll 4
        for (int m = lane; m < 256; m += 32) dstW[m] = __ldcg(&srcW[m]);
        if (l > 0) {
            const uint4* srcU = reinterpret_cast<const uint4*>(
                g_UHb8 + (size_t)((l - 1) * H + i) * 4096);
            uint4* dstU = reinterpret_cast<uint4*>(smem + woff + 4096);
#pragma unroll 4
            for (int m = lane; m < 256; m += 32) dstU[m] = __ldcg(&srcU[m]);
        }
    }

    // ---- per-task constants & state ----
    float bfv = 0.f, bgv = 0.f, bqv = 0.f, bcv = 0.f;
    if (valid) { bfv = Bf[bi]; bgv = Bg[bi]; bqv = Bq[bi]; bcv = Bc[bi]; }
    float s_state = 0.f;

    const uint4* wsm = reinterpret_cast<const uint4*>(smem + woff);
    const uint4* usm = reinterpret_cast<const uint4*>(smem + woff + 4096);
    __syncthreads();

    for (int step = 0; step < NSTEPS; ++step) {
        // ---- stage previous-step h (4 vectors, fp16) into SMEM split layout ----
        if (tid < 512) {
            const uint4* hg = reinterpret_cast<const uint4*>(g_hh[step & 1]);
            uint4 val = __ldcg(hg + tid);
            int v = tid >> 7, m = tid & 127;
            int dst = (m >> 6) * 64 + (m & 1) * 32 + ((m & 63) >> 1);
            reinterpret_cast<uint4*>(sh_h)[v * 128 + dst] = val;
        }
        __syncthreads();

        const int t = step - l;
        if (valid && (unsigned)t < (unsigned)SEQ) {
            __half2 acc2[4];
            const __half2 hz = __float2half2_rn(0.f);
            acc2[0] = hz; acc2[1] = hz; acc2[2] = hz; acc2[3] = hz;

            mv_smem(wsm, reinterpret_cast<const uint4*>(sh_h + l * 2048), lane, acc2);
            if (l > 0)
                mv_smem(usm, reinterpret_cast<const uint4*>(sh_h + (l - 1) * 2048),
                        lane, acc2);

            float acc[4];
#pragma unroll
            for (int g = 0; g < 4; ++g) {
                float2 f = __half22float2(acc2[g]);
                acc[g] = f.x + f.y;
            }
#pragma unroll
            for (int off = 16; off > 0; off >>= 1) {
                acc[0] += __shfl_xor_sync(0xffffffffu, acc[0], off);
                acc[1] += __shfl_xor_sync(0xffffffffu, acc[1], off);
                acc[2] += __shfl_xor_sync(0xffffffffu, acc[2], off);
                acc[3] += __shfl_xor_sync(0xffffffffu, acc[3], off);
            }

            if (lane == 0) {
                float zf = acc[0] + bfv;
                float zg = acc[1] + bgv;
                float zq = acc[2] + bqv;
                float zc = acc[3] + bcv;
                if (l == 0) {
                    const float* zin = g_Zin + (size_t)t * (4 * H);
                    zf += zin[i];
                    zg += zin[H + i];
                    zq += zin[2 * H + i];
                    zc += zin[3 * H + i];
                }
                float f  = 1.f / (1.f + __expf(-zf));
                float gg = 1.f / (1.f + __expf(-zg));
                float q  = 1.f / (1.f + __expf(-zq));
                float cd = 1.f / (1.f + __expf(-zc));
                s_state = fmaf(f, s_state, gg * cd);
                float hn = tanhf(s_state) * q;
                __half hh = __float2half_rn(hn);
                unsigned short hb16 = *reinterpret_cast<unsigned short*>(&hh);
                asm volatile("st.global.cg.u16 [%0], %1;"
                             :: "l"(&g_hh[(step + 1) & 1][bi]), "h"(hb16));
                if (t == SEQ - 1) out[bi] = hn;
            }
        }
        grid_barrier();
    }
}

// ------------------------- launch ---------------------------------------------
extern "C" void kernel_launch(void* const* d_in, const int* in_sizes, int n_in,
                              void* d_out, int out_size)
{
    const float* x   = (const float*)d_in[0];
    const float* Uf  = (const float*)d_in[1];
    const float* UHf = (const float*)d_in[2];
    const float* Wf  = (const float*)d_in[3];
    const float* Bf  = (const float*)d_in[4];
    const float* Ug  = (const float*)d_in[5];
    const float* UHg = (const float*)d_in[6];
    const float* Wg  = (const float*)d_in[7];
    const float* Bg  = (const float*)d_in[8];
    const float* Uq  = (const float*)d_in[9];
    const float* UHq = (const float*)d_in[10];
    const float* Wq  = (const float*)d_in[11];
    const float* Bq  = (const float*)d_in[12];
    const float* Uc  = (const float*)d_in[13];
    const float* UHc = (const float*)d_in[14];
    const float* Wc  = (const float*)d_in[15];
    const float* Bc  = (const float*)d_in[16];
    float* out = (float*)d_out;

    cudaFuncSetAttribute(lstm_main, cudaFuncAttributeMaxDynamicSharedMemorySize,
                         SMEM_BYTES);

    const size_t TOTAL = (size_t)L * H * 4 * H + (size_t)(L - 1) * H * 4 * H;
    int pb = (int)((TOTAL + 1023) / 1024);
    prep_weights<<<pb, 1024>>>(Wf, Wg, Wq, Wc, UHf, UHg, UHq, UHc);
    init_state<<<1, 1024>>>();

    dim3 gg(4 * H / BN, SEQ / BM);
    gemm_zin<<<gg, 256>>>(x, Uf, Ug, Uq, Uc);

    lstm_main<<<NBLOCKS, NTHREADS, SMEM_BYTES>>>(Bf, Bg, Bq, Bc, out);
}